// round 1
// baseline (speedup 1.0000x reference)
#include <cuda_runtime.h>
#include <math.h>
#include <stdint.h>

// Problem constants (fixed shapes per reference)
#define HEAD_DIM   128
#define NUM_HEADS  32
#define KVH        8
#define G          4            // NUM_HEADS / KVH
#define BLOCK_SZ   16
#define D_KV       (KVH * HEAD_DIM)   // 1024
#define MAX_BPS    128
#define MAX_CTX    2048
#define NUM_BLOCKS 4096
#define NSLOTS     (NUM_BLOCKS * BLOCK_SZ)   // 65536
#define BATCH      32
#define CHUNK      256
#define NCHUNK     (MAX_CTX / CHUNK)         // 8
#define SCALE_F    0.08838834764831845f

// Device-global scratch (allocation-free rule: no cudaMalloc allowed)
__device__ int   g_inv[NSLOTS];                                   // 256 KB
__device__ float g_pm  [BATCH * KVH * NCHUNK * G];                // 32 KB
__device__ float g_pl  [BATCH * KVH * NCHUNK * G];                // 32 KB
__device__ float g_pacc[BATCH * KVH * NCHUNK * G * HEAD_DIM];     // 4 MB

// ---------------------------------------------------------------------------
// Kernel 1: inverse slot map. inv[flat] = r if slot_mapping[r]==flat else -1.
// B is tiny (32); the scan is trivial and race-free.
// ---------------------------------------------------------------------------
__global__ void inv_kernel(const int* __restrict__ slot, int B) {
    int i = blockIdx.x * blockDim.x + threadIdx.x;
    if (i >= NSLOTS) return;
    int r = -1;
    for (int j = 0; j < B; j++) {
        if (slot[j] == i) r = j;   // last write wins (matches scatter)
    }
    g_inv[i] = r;
}

__device__ __forceinline__ float dot4(float4 a, float4 b) {
    return a.x * b.x + a.y * b.y + a.z * b.z + a.w * b.w;
}

// ---------------------------------------------------------------------------
// Kernel 2: split-KV flash-decode attention.
// grid = (NCHUNK, KVH, B), block = 128 threads.
// Thread mapping for scores: t = tid>>3 (token in 16-block), part = tid&7
// (16-dim slice). Thread mapping for V accumulate: d = tid.
// ---------------------------------------------------------------------------
__global__ void __launch_bounds__(128) attn_kernel(
    const float* __restrict__ q,
    const float* __restrict__ knew,
    const float* __restrict__ vnew,
    const float* __restrict__ kc,
    const float* __restrict__ vc,
    const int*   __restrict__ bt,
    const int*   __restrict__ ctx_lens)
{
    const int b     = blockIdx.z;
    const int h     = blockIdx.y;
    const int chunk = blockIdx.x;

    const int ctx   = ctx_lens[b];
    const int start = chunk * CHUNK;
    if (start >= ctx) return;
    const int end = (start + CHUNK < ctx) ? (start + CHUNK) : ctx;
    const int nb  = (end - start + BLOCK_SZ - 1) / BLOCK_SZ;

    const int tid  = threadIdx.x;
    const int t    = tid >> 3;     // token 0..15 in current cache block
    const int part = tid & 7;      // dim slice [part*16, part*16+16)
    const int w    = tid >> 5;     // warp 0..3
    const int lane = tid & 31;

    __shared__ float v_sh[BLOCK_SZ][HEAD_DIM];   // 8 KB
    __shared__ float s_sh[G][BLOCK_SZ];
    __shared__ float p_sh[G][BLOCK_SZ];
    __shared__ float st_m[G], st_l[G], alpha_sh[G];

    // q slice in registers: 4 heads x 16 dims (part*16 .. part*16+15)
    float4 qr[G][4];
    #pragma unroll
    for (int g = 0; g < G; g++) {
        const float4* qp = (const float4*)(q + ((size_t)b * NUM_HEADS + (size_t)(h * G + g)) * HEAD_DIM + part * 16);
        #pragma unroll
        for (int l = 0; l < 4; l++) qr[g][l] = qp[l];
    }

    if (tid < G) { st_m[tid] = -3.0e38f; st_l[tid] = 0.0f; }
    // (no sync needed: st_m/st_l are touched only by threads 0..3 until
    //  values derived from them pass through synced alpha_sh/p_sh)

    float acc[G];
    #pragma unroll
    for (int g = 0; g < G; g++) acc[g] = 0.0f;

    const int j0 = start >> 4;   // first cache-block index in block table

    for (int jj = 0; jj < nb; jj++) {
        const int phys = __ldg(&bt[b * MAX_BPS + j0 + jj]);

        // ---- K: load my token row slice straight to registers, dot with q ----
        {
            const int flat = phys * BLOCK_SZ + t;
            const int r    = g_inv[flat];
            const float* krow = (r >= 0)
                ? (knew + ((size_t)r * KVH + h) * HEAD_DIM)
                : (kc + (size_t)flat * D_KV + (size_t)h * HEAD_DIM);
            const float4* kp = (const float4*)(krow + part * 16);
            float4 k0 = kp[0], k1 = kp[1], k2 = kp[2], k3 = kp[3];

            float s[G];
            #pragma unroll
            for (int g = 0; g < G; g++) {
                s[g] = dot4(qr[g][0], k0) + dot4(qr[g][1], k1)
                     + dot4(qr[g][2], k2) + dot4(qr[g][3], k3);
            }
            // reduce over the 8 lanes sharing this token
            #pragma unroll
            for (int g = 0; g < G; g++) {
                s[g] += __shfl_xor_sync(0xffffffffu, s[g], 1);
                s[g] += __shfl_xor_sync(0xffffffffu, s[g], 2);
                s[g] += __shfl_xor_sync(0xffffffffu, s[g], 4);
            }
            const int tok = start + jj * BLOCK_SZ + t;
            if (part == 0) {
                #pragma unroll
                for (int g = 0; g < G; g++)
                    s_sh[g][t] = (tok < ctx) ? s[g] * SCALE_F : -1.0e30f;
            }
        }

        // ---- V: stage block to smem (warp w handles rows w, w+4, w+8, w+12) ----
        #pragma unroll
        for (int l = 0; l < 4; l++) {
            const int tv   = w + l * 4;
            const int flat = phys * BLOCK_SZ + tv;
            const int r    = g_inv[flat];
            const float* vrow = (r >= 0)
                ? (vnew + ((size_t)r * KVH + h) * HEAD_DIM)
                : (vc + (size_t)flat * D_KV + (size_t)h * HEAD_DIM);
            ((float4*)&v_sh[tv][0])[lane] = ((const float4*)vrow)[lane];
        }
        __syncthreads();

        // ---- online softmax update (one thread per head) ----
        if (tid < G) {
            const int g = tid;
            float m_old = st_m[g];
            float mb = m_old;
            #pragma unroll
            for (int tt = 0; tt < BLOCK_SZ; tt++) mb = fmaxf(mb, s_sh[g][tt]);
            float alpha = __expf(m_old - mb);
            float sum = 0.0f;
            #pragma unroll
            for (int tt = 0; tt < BLOCK_SZ; tt++) {
                float p = __expf(s_sh[g][tt] - mb);
                p_sh[g][tt] = p;
                sum += p;
            }
            st_l[g] = st_l[g] * alpha + sum;
            st_m[g] = mb;
            alpha_sh[g] = alpha;
        }
        __syncthreads();

        // ---- accumulate: thread owns output dim d = tid ----
        {
            float a0 = alpha_sh[0], a1 = alpha_sh[1], a2 = alpha_sh[2], a3 = alpha_sh[3];
            acc[0] *= a0; acc[1] *= a1; acc[2] *= a2; acc[3] *= a3;
            #pragma unroll
            for (int tt = 0; tt < BLOCK_SZ; tt++) {
                float vv = v_sh[tt][tid];
                acc[0] += p_sh[0][tt] * vv;
                acc[1] += p_sh[1][tt] * vv;
                acc[2] += p_sh[2][tt] * vv;
                acc[3] += p_sh[3][tt] * vv;
            }
        }
        __syncthreads();   // protect v_sh / p_sh / s_sh before next iteration
    }

    // ---- write chunk partials ----
    const int base = ((b * KVH + h) * NCHUNK + chunk) * G;
    #pragma unroll
    for (int g = 0; g < G; g++)
        g_pacc[(size_t)(base + g) * HEAD_DIM + tid] = acc[g];
    if (tid < G) {
        g_pm[base + tid] = st_m[tid];
        g_pl[base + tid] = st_l[tid];
    }
}

// ---------------------------------------------------------------------------
// Kernel 3: combine chunk partials with log-sum-exp weights.
// grid = B*KVH, block = 128 (thread = dim).
// ---------------------------------------------------------------------------
__global__ void __launch_bounds__(128) reduce_kernel(
    float* __restrict__ out, const int* __restrict__ ctx_lens)
{
    const int bh = blockIdx.x;
    const int b  = bh / KVH;
    const int h  = bh % KVH;
    const int d  = threadIdx.x;

    const int ctx = ctx_lens[b];
    const int nv  = (ctx + CHUNK - 1) / CHUNK;

    #pragma unroll
    for (int g = 0; g < G; g++) {
        const int base0 = (b * KVH + h) * NCHUNK * G + g;
        float M = -3.0e38f;
        for (int c = 0; c < nv; c++) M = fmaxf(M, g_pm[base0 + c * G]);
        float L = 0.0f, o = 0.0f;
        for (int c = 0; c < nv; c++) {
            float wgt = __expf(g_pm[base0 + c * G] - M);
            L += wgt * g_pl[base0 + c * G];
            o += wgt * g_pacc[(size_t)(base0 + c * G) * HEAD_DIM + d];
        }
        out[((size_t)b * NUM_HEADS + (size_t)(h * G + g)) * HEAD_DIM + d] = o / L;
    }
}

// ---------------------------------------------------------------------------
// Launch: inverse map -> split-KV attention -> LSE reduce. Graph-capturable
// (kernel launches only, no allocation, no sync).
// ---------------------------------------------------------------------------
extern "C" void kernel_launch(void* const* d_in, const int* in_sizes, int n_in,
                              void* d_out, int out_size) {
    const float* q    = (const float*)d_in[0];
    const float* k    = (const float*)d_in[1];
    const float* v    = (const float*)d_in[2];
    const float* kc   = (const float*)d_in[3];
    const float* vc   = (const float*)d_in[4];
    const int*   slot = (const int*)d_in[5];
    const int*   bt   = (const int*)d_in[6];
    const int*   ctx  = (const int*)d_in[7];

    const int B = in_sizes[5];   // 32

    inv_kernel<<<(NSLOTS + 255) / 256, 256>>>(slot, B);

    dim3 grid(NCHUNK, KVH, B);
    attn_kernel<<<grid, 128>>>(q, k, v, kc, vc, bt, ctx);

    reduce_kernel<<<B * KVH, HEAD_DIM>>>((float*)d_out, ctx);
}